// round 8
// baseline (speedup 1.0000x reference)
#include <cuda_runtime.h>
#include <cuda_fp16.h>
#include <cstdint>

#define NN 100000      // nodes
#define DD 64          // feature dim
#define EE 1250000     // edges
#define ND (NN * DD)
#define NH4 (ND / 8)   // uint4 count for fp16 feature arrays (8 halfs per uint4)
#define WMAX 64        // ELL width; P(Poisson(12.5) >= 64) ~ 1e-23

typedef unsigned long long ull;

// ---------------- scratch (device globals, allocation-free) ----------------
__device__ int   g_cnt0[NN];
__device__ int   g_cnt1[NN];
__device__ float g_degf[NN];
__device__ float g_dis[NN];
__device__ int2  g_ell0[(size_t)NN * WMAX];  // edge graph: {col, w} -> {col, w_norm} after L1
__device__ int2  g_ell1[(size_t)NN * WMAX];  // nb graph:   {col, w}
__device__ uint4 g_xh[NH4];      // x fp16
__device__ uint4 g_lxh[NH4];     // Lx fp16
__device__ uint4 g_outh[NH4];    // out fp16
__device__ uint4 g_b1h[NH4];     // N(out) fp16
__device__ uint4 g_b2h[NH4];     // N(out[shuf]) fp16

// ---------------- helpers ----------------
__device__ __forceinline__ ull packf2(float a, float b) {
    ull u;
    asm("mov.b64 %0, {%1, %2};" : "=l"(u) : "f"(a), "f"(b));
    return u;
}

__device__ __forceinline__ float2 unpackf2(ull u) {
    float2 f;
    asm("mov.b64 {%0, %1}, %2;" : "=f"(f.x), "=f"(f.y) : "l"(u));
    return f;
}

// acc[k] (f32x2) += half2[k](v) * w2   — 4x packed FFMA2 per uint4
__device__ __forceinline__ void fma8(ull* acc, uint4 v, ull w2) {
    const __half2* h = (const __half2*)&v;
#pragma unroll
    for (int k = 0; k < 4; k++) {
        float2 f = __half22float2(h[k]);
        ull fv = packf2(f.x, f.y);
        asm("fma.rn.f32x2 %0, %1, %2, %0;" : "+l"(acc[k]) : "l"(fv), "l"(w2));
    }
}

// pack 8 floats (4 f32x2 accs) into uint4 of halves
__device__ __forceinline__ uint4 packh8(const ull* acc) {
    uint4 u;
    unsigned* p = (unsigned*)&u;
#pragma unroll
    for (int k = 0; k < 4; k++) {
        float2 f = unpackf2(acc[k]);
        __half2 h = __floats2half2_rn(f.x, f.y);
        p[k] = *reinterpret_cast<unsigned*>(&h);
    }
    return u;
}

__device__ __forceinline__ void unpackh8(uint4 v, float* o) {
    const __half2* h = (const __half2*)&v;
#pragma unroll
    for (int k = 0; k < 4; k++) {
        float2 f = __half22float2(h[k]);
        o[2 * k]     = f.x;
        o[2 * k + 1] = f.y;
    }
}

// ---------------- build: fused ELL append (both graphs) + fp16 x ----------------
__global__ void append_all_kernel(const int* __restrict__ er, const int* __restrict__ ec,
                                  const float* __restrict__ ew,
                                  const int* __restrict__ nr, const int* __restrict__ nc,
                                  const float* __restrict__ nw,
                                  const float* __restrict__ x) {
    int i = blockIdx.x * blockDim.x + threadIdx.x;
    if (i < EE) {
        int r = er[i];
        float w = ew[i];
        atomicAdd(&g_degf[r], w);
        int p = atomicAdd(&g_cnt0[r], 1);
        g_ell0[(size_t)r * WMAX + p] = make_int2(ec[i], __float_as_int(w));
    } else if (i < 2 * EE) {
        int k = i - EE;
        int r = nr[k];
        int p = atomicAdd(&g_cnt1[r], 1);
        g_ell1[(size_t)r * WMAX + p] = make_int2(nc[k], __float_as_int(nw[k]));
    } else if (i < 2 * EE + NH4) {
        int k = i - 2 * EE;
        const float* p = x + (size_t)k * 8;
        uint4 u;
        unsigned* up = (unsigned*)&u;
#pragma unroll
        for (int q = 0; q < 4; q++) {
            __half2 h = __floats2half2_rn(p[2 * q], p[2 * q + 1]);
            up[q] = *reinterpret_cast<unsigned*>(&h);
        }
        g_xh[k] = u;
    }
}

__global__ void dis_kernel() {
    int i = blockIdx.x * blockDim.x + threadIdx.x;
    if (i < NN) {
        float d = g_degf[i];
        g_dis[i] = (d > 0.f) ? rsqrtf(d) : 0.f;
    }
}

// ---------------- SPMM kernels: 8 lanes per row, 8 features per lane ----------------

// Lx = x - Anorm x; normalizes weights in-place and writes lxh fp16
__global__ void spmm_L1_kernel(const float* __restrict__ x) {
    int t = blockIdx.x * blockDim.x + threadIdx.x;
    int r = t >> 3;
    if (r >= NN) return;
    unsigned lane = t & 7;
    int deg = g_cnt0[r];
    float dr = g_dis[r];
    const size_t base = (size_t)r * WMAX;
    ull acc[4] = {0, 0, 0, 0};
    int j = 0;
    for (; j + 2 <= deg; j += 2) {
        int2 e0 = g_ell0[base + j], e1 = g_ell0[base + j + 1];
        float d0 = __ldg(&g_dis[e0.x]);
        float d1 = __ldg(&g_dis[e1.x]);
        uint4 v0 = g_xh[(unsigned)e0.x * 8u + lane];
        uint4 v1 = g_xh[(unsigned)e1.x * 8u + lane];
        float w0 = dr * __int_as_float(e0.y) * d0;
        float w1 = dr * __int_as_float(e1.y) * d1;
        if (lane == 0) {
            g_ell0[base + j].y     = __float_as_int(w0);
            g_ell0[base + j + 1].y = __float_as_int(w1);
        }
        fma8(acc, v0, packf2(w0, w0));
        fma8(acc, v1, packf2(w1, w1));
    }
    if (j < deg) {
        int2 e0 = g_ell0[base + j];
        float w0 = dr * __int_as_float(e0.y) * __ldg(&g_dis[e0.x]);
        if (lane == 0) g_ell0[base + j].y = __float_as_int(w0);
        uint4 v0 = g_xh[(unsigned)e0.x * 8u + lane];
        fma8(acc, v0, packf2(w0, w0));
    }
    // Lx = x - acc
    const float* xp = x + (size_t)r * DD + lane * 8;
    uint4 u;
    unsigned* up = (unsigned*)&u;
#pragma unroll
    for (int k = 0; k < 4; k++) {
        float2 a = unpackf2(acc[k]);
        __half2 h = __floats2half2_rn(xp[2 * k] - a.x, xp[2 * k + 1] - a.y);
        up[k] = *reinterpret_cast<unsigned*>(&h);
    }
    g_lxh[(unsigned)r * 8u + lane] = u;
}

// out = c0*x + c1*Lx + c2*(Lx - Anorm*Lx); writes out fp32 + outh fp16
__global__ void spmm_L2_kernel(const float* __restrict__ x,
                               const float* __restrict__ temp,
                               float* __restrict__ out) {
    int t = blockIdx.x * blockDim.x + threadIdx.x;
    int r = t >> 3;
    if (r >= NN) return;
    unsigned lane = t & 7;
    int deg = g_cnt0[r];
    const size_t base = (size_t)r * WMAX;
    ull acc[4] = {0, 0, 0, 0};
    int j = 0;
    for (; j + 2 <= deg; j += 2) {
        int2 e0 = g_ell0[base + j], e1 = g_ell0[base + j + 1];
        uint4 v0 = g_lxh[(unsigned)e0.x * 8u + lane];
        uint4 v1 = g_lxh[(unsigned)e1.x * 8u + lane];
        float w0 = __int_as_float(e0.y), w1 = __int_as_float(e1.y);
        fma8(acc, v0, packf2(w0, w0));
        fma8(acc, v1, packf2(w1, w1));
    }
    if (j < deg) {
        int2 e0 = g_ell0[base + j];
        uint4 v0 = g_lxh[(unsigned)e0.x * 8u + lane];
        float w0 = __int_as_float(e0.y);
        fma8(acc, v0, packf2(w0, w0));
    }
    float t0 = fmaxf(__ldg(temp + 0), 0.f);
    float t1 = fmaxf(__ldg(temp + 1), 0.f);
    float t2 = fmaxf(__ldg(temp + 2), 0.f);
    float c0 = t0;
    float c1 = t1 - t0;
    float c2 = (t0 + t2 - 2.f * t1) * 0.25f;
    const float* xp = x + (size_t)r * DD + lane * 8;
    float lv[8];
    unpackh8(g_lxh[(unsigned)r * 8u + lane], lv);
    float* op = out + (size_t)r * DD + lane * 8;
    uint4 u;
    unsigned* up = (unsigned*)&u;
#pragma unroll
    for (int k = 0; k < 4; k++) {
        float2 a = unpackf2(acc[k]);
        float o0 = c0 * xp[2 * k]     + c1 * lv[2 * k]     + c2 * (lv[2 * k]     - a.x);
        float o1 = c0 * xp[2 * k + 1] + c1 * lv[2 * k + 1] + c2 * (lv[2 * k + 1] - a.y);
        op[2 * k]     = o0;
        op[2 * k + 1] = o1;
        __half2 h = __floats2half2_rn(o0, o1);
        up[k] = *reinterpret_cast<unsigned*>(&h);
    }
    g_outh[(unsigned)r * 8u + lane] = u;
}

// dual hop 1: b1h[r] = sum w*outh[col]; b2h[r] = sum w*outh[shuf[col]]
__global__ void spmm_N1_kernel(const int* __restrict__ shuf) {
    int t = blockIdx.x * blockDim.x + threadIdx.x;
    int r = t >> 3;
    if (r >= NN) return;
    unsigned lane = t & 7;
    int deg = g_cnt1[r];
    const size_t base = (size_t)r * WMAX;
    ull ap[4] = {0, 0, 0, 0};
    ull an[4] = {0, 0, 0, 0};
    int j = 0;
    for (; j + 2 <= deg; j += 2) {
        int2 e0 = g_ell1[base + j], e1 = g_ell1[base + j + 1];
        int c0 = e0.x, c1 = e1.x;
        int s0 = __ldg(shuf + c0);
        int s1 = __ldg(shuf + c1);
        ull w0 = packf2(__int_as_float(e0.y), __int_as_float(e0.y));
        ull w1 = packf2(__int_as_float(e1.y), __int_as_float(e1.y));
        uint4 vp0 = g_outh[(unsigned)c0 * 8u + lane];
        uint4 vp1 = g_outh[(unsigned)c1 * 8u + lane];
        uint4 vn0 = g_outh[(unsigned)s0 * 8u + lane];
        uint4 vn1 = g_outh[(unsigned)s1 * 8u + lane];
        fma8(ap, vp0, w0);
        fma8(ap, vp1, w1);
        fma8(an, vn0, w0);
        fma8(an, vn1, w1);
    }
    if (j < deg) {
        int2 e0 = g_ell1[base + j];
        int c0 = e0.x;
        int s0 = __ldg(shuf + c0);
        ull w0 = packf2(__int_as_float(e0.y), __int_as_float(e0.y));
        uint4 vp0 = g_outh[(unsigned)c0 * 8u + lane];
        uint4 vn0 = g_outh[(unsigned)s0 * 8u + lane];
        fma8(ap, vp0, w0);
        fma8(an, vn0, w0);
    }
    g_b1h[(unsigned)r * 8u + lane] = packh8(ap);
    g_b2h[(unsigned)r * 8u + lane] = packh8(an);
}

// dual hop 2: zp[r] = sum w*b1h[col]; zn[r] = sum w*b2h[col] (fp32 out)
__global__ void spmm_N2_kernel(float* __restrict__ zp, float* __restrict__ zn) {
    int t = blockIdx.x * blockDim.x + threadIdx.x;
    int r = t >> 3;
    if (r >= NN) return;
    unsigned lane = t & 7;
    int deg = g_cnt1[r];
    const size_t base = (size_t)r * WMAX;
    ull ap[4] = {0, 0, 0, 0};
    ull an[4] = {0, 0, 0, 0};
    int j = 0;
    for (; j + 2 <= deg; j += 2) {
        int2 e0 = g_ell1[base + j], e1 = g_ell1[base + j + 1];
        ull w0 = packf2(__int_as_float(e0.y), __int_as_float(e0.y));
        ull w1 = packf2(__int_as_float(e1.y), __int_as_float(e1.y));
        uint4 vp0 = g_b1h[(unsigned)e0.x * 8u + lane];
        uint4 vn0 = g_b2h[(unsigned)e0.x * 8u + lane];
        uint4 vp1 = g_b1h[(unsigned)e1.x * 8u + lane];
        uint4 vn1 = g_b2h[(unsigned)e1.x * 8u + lane];
        fma8(ap, vp0, w0);
        fma8(an, vn0, w0);
        fma8(ap, vp1, w1);
        fma8(an, vn1, w1);
    }
    if (j < deg) {
        int2 e0 = g_ell1[base + j];
        ull w0 = packf2(__int_as_float(e0.y), __int_as_float(e0.y));
        uint4 vp0 = g_b1h[(unsigned)e0.x * 8u + lane];
        uint4 vn0 = g_b2h[(unsigned)e0.x * 8u + lane];
        fma8(ap, vp0, w0);
        fma8(an, vn0, w0);
    }
    float* pp = zp + (size_t)r * DD + lane * 8;
    float* pn = zn + (size_t)r * DD + lane * 8;
#pragma unroll
    for (int k = 0; k < 4; k++) {
        float2 a = unpackf2(ap[k]);
        pp[2 * k]     = a.x;
        pp[2 * k + 1] = a.y;
        float2 b = unpackf2(an[k]);
        pn[2 * k]     = b.x;
        pn[2 * k + 1] = b.y;
    }
}

extern "C" void kernel_launch(void* const* d_in, const int* in_sizes, int n_in,
                              void* d_out, int out_size) {
    const float* x    = (const float*)d_in[0];
    const int*   shuf = (const int*)  d_in[1];
    const int*   ei   = (const int*)  d_in[2];
    const float* ew   = (const float*)d_in[3];
    const int*   ni   = (const int*)  d_in[4];
    const float* nw   = (const float*)d_in[5];
    const float* temp = (const float*)d_in[6];
    float* out = (float*)d_out;   // [out | z_pos | z_neg]

    const int* erow = ei;
    const int* ecol = ei + EE;
    const int* nrow = ni;
    const int* ncol = ni + EE;

    void *p_cnt0, *p_cnt1, *p_degf;
    cudaGetSymbolAddress(&p_cnt0, g_cnt0);
    cudaGetSymbolAddress(&p_cnt1, g_cnt1);
    cudaGetSymbolAddress(&p_degf, g_degf);

    const int TB = 256;
    const int blkN   = (NN + TB - 1) / TB;
    const int blkALL = (2 * EE + NH4 + TB - 1) / TB;
    const int blkR8  = (NN * 8 + TB - 1) / TB;

    // ---- build: zero counters, fused append (both graphs) + fp16 x, dis ----
    cudaMemsetAsync(p_cnt0, 0, NN * sizeof(int), 0);
    cudaMemsetAsync(p_cnt1, 0, NN * sizeof(int), 0);
    cudaMemsetAsync(p_degf, 0, NN * sizeof(float), 0);
    append_all_kernel<<<blkALL, TB>>>(erow, ecol, ew, nrow, ncol, nw, x);
    dis_kernel<<<blkN, TB>>>();

    // ---- spectral polynomial ----
    spmm_L1_kernel<<<blkR8, TB>>>(x);
    spmm_L2_kernel<<<blkR8, TB>>>(x, temp, out);

    // ---- z_pos / z_neg ----
    spmm_N1_kernel<<<blkR8, TB>>>(shuf);
    spmm_N2_kernel<<<blkR8, TB>>>(out + (size_t)ND, out + 2 * (size_t)ND);
}

// round 9
// speedup vs baseline: 1.3059x; 1.3059x over previous
#include <cuda_runtime.h>
#include <cuda_fp16.h>
#include <cstdint>

#define NN 100000      // nodes
#define DD 64          // feature dim
#define EE 1250000     // edges
#define ND (NN * DD)
#define NH2 (ND / 4)   // uint2 count for fp16 feature arrays (4 halfs per uint2)
#define WMAX 64        // ELL width; P(Poisson(12.5) >= 64) ~ 1e-23

// ---------------- scratch (device globals, allocation-free) ----------------
__device__ int   g_cnt0[NN];
__device__ int   g_cnt1[NN];
__device__ float g_degf[NN];
__device__ float g_dis[NN];
__device__ int2  g_ell0[(size_t)NN * WMAX];  // edge graph: {col, w} -> {col, w_norm} after L1
__device__ int2  g_ell1[(size_t)NN * WMAX];  // nb graph:   {col, w}
__device__ uint2 g_xh[NH2];      // x fp16
__device__ uint2 g_lxh[NH2];     // Lx fp16
__device__ uint2 g_outh[NH2];    // out fp16
__device__ uint2 g_b1h[NH2];     // N(out) fp16
__device__ uint2 g_b2h[NH2];     // N(out[shuf]) fp16

// ---------------- helpers ----------------
__device__ __forceinline__ void fma4(float* acc, uint2 v, float w) {
    __half2 h0 = *reinterpret_cast<__half2*>(&v.x);
    __half2 h1 = *reinterpret_cast<__half2*>(&v.y);
    float2 f0 = __half22float2(h0);
    float2 f1 = __half22float2(h1);
    acc[0] += w * f0.x;
    acc[1] += w * f0.y;
    acc[2] += w * f1.x;
    acc[3] += w * f1.y;
}

__device__ __forceinline__ float4 unpack4(uint2 v) {
    __half2 h0 = *reinterpret_cast<__half2*>(&v.x);
    __half2 h1 = *reinterpret_cast<__half2*>(&v.y);
    float2 f0 = __half22float2(h0);
    float2 f1 = __half22float2(h1);
    return make_float4(f0.x, f0.y, f1.x, f1.y);
}

__device__ __forceinline__ uint2 pack4(float a, float b, float c, float d) {
    uint2 u;
    __half2 h0 = __floats2half2_rn(a, b);
    __half2 h1 = __floats2half2_rn(c, d);
    u.x = *reinterpret_cast<unsigned*>(&h0);
    u.y = *reinterpret_cast<unsigned*>(&h1);
    return u;
}

// ---------------- build: fused ELL append (both graphs) + fp16 x ----------------
__global__ void append_all_kernel(const int* __restrict__ er, const int* __restrict__ ec,
                                  const float* __restrict__ ew,
                                  const int* __restrict__ nr, const int* __restrict__ nc,
                                  const float* __restrict__ nw,
                                  const float* __restrict__ x) {
    int i = blockIdx.x * blockDim.x + threadIdx.x;
    if (i < EE) {
        int r = er[i];
        float w = ew[i];
        atomicAdd(&g_degf[r], w);
        int p = atomicAdd(&g_cnt0[r], 1);
        g_ell0[(size_t)r * WMAX + p] = make_int2(ec[i], __float_as_int(w));
    } else if (i < 2 * EE) {
        int k = i - EE;
        int r = nr[k];
        int p = atomicAdd(&g_cnt1[r], 1);
        g_ell1[(size_t)r * WMAX + p] = make_int2(nc[k], __float_as_int(nw[k]));
    } else if (i < 2 * EE + NH2) {
        int k = i - 2 * EE;
        float4 v = *(const float4*)(x + (size_t)k * 4);
        g_xh[k] = pack4(v.x, v.y, v.z, v.w);
    }
}

__global__ void dis_kernel() {
    int i = blockIdx.x * blockDim.x + threadIdx.x;
    if (i < NN) {
        float d = g_degf[i];
        g_dis[i] = (d > 0.f) ? rsqrtf(d) : 0.f;
    }
}

// ---------------- SPMM kernels: 16 lanes per row, 4 features per lane ----------------

// Lx = x - Anorm x; normalizes weights in-place and writes lxh fp16
__global__ void spmm_L1_kernel(const float* __restrict__ x) {
    int t = blockIdx.x * blockDim.x + threadIdx.x;
    int r = t >> 4;
    if (r >= NN) return;
    unsigned lane = t & 15;
    int deg = g_cnt0[r];
    float dr = g_dis[r];
    const size_t base = (size_t)r * WMAX;
    float acc[4] = {0.f, 0.f, 0.f, 0.f};
    int j = 0;
    for (; j + 4 <= deg; j += 4) {
        int2 e0 = g_ell0[base + j],     e1 = g_ell0[base + j + 1];
        int2 e2 = g_ell0[base + j + 2], e3 = g_ell0[base + j + 3];
        float d0 = __ldg(&g_dis[e0.x]);
        float d1 = __ldg(&g_dis[e1.x]);
        float d2 = __ldg(&g_dis[e2.x]);
        float d3 = __ldg(&g_dis[e3.x]);
        uint2 v0 = g_xh[(unsigned)e0.x * 16u + lane];
        uint2 v1 = g_xh[(unsigned)e1.x * 16u + lane];
        uint2 v2 = g_xh[(unsigned)e2.x * 16u + lane];
        uint2 v3 = g_xh[(unsigned)e3.x * 16u + lane];
        float w0 = dr * __int_as_float(e0.y) * d0;
        float w1 = dr * __int_as_float(e1.y) * d1;
        float w2 = dr * __int_as_float(e2.y) * d2;
        float w3 = dr * __int_as_float(e3.y) * d3;
        if (lane == 0) {
            g_ell0[base + j].y     = __float_as_int(w0);
            g_ell0[base + j + 1].y = __float_as_int(w1);
            g_ell0[base + j + 2].y = __float_as_int(w2);
            g_ell0[base + j + 3].y = __float_as_int(w3);
        }
        fma4(acc, v0, w0);
        fma4(acc, v1, w1);
        fma4(acc, v2, w2);
        fma4(acc, v3, w3);
    }
    for (; j < deg; j++) {
        int2 e0 = g_ell0[base + j];
        float w0 = dr * __int_as_float(e0.y) * __ldg(&g_dis[e0.x]);
        if (lane == 0) g_ell0[base + j].y = __float_as_int(w0);
        uint2 v0 = g_xh[(unsigned)e0.x * 16u + lane];
        fma4(acc, v0, w0);
    }
    float4 xv = *(const float4*)(x + (size_t)r * DD + lane * 4u);
    g_lxh[(unsigned)r * 16u + lane] =
        pack4(xv.x - acc[0], xv.y - acc[1], xv.z - acc[2], xv.w - acc[3]);
}

// out = c0*x + c1*Lx + c2*(Lx - Anorm*Lx); writes out fp32 + outh fp16
__global__ void spmm_L2_kernel(const float* __restrict__ x,
                               const float* __restrict__ temp,
                               float* __restrict__ out) {
    int t = blockIdx.x * blockDim.x + threadIdx.x;
    int r = t >> 4;
    if (r >= NN) return;
    unsigned lane = t & 15;
    int deg = g_cnt0[r];
    const size_t base = (size_t)r * WMAX;
    float acc[4] = {0.f, 0.f, 0.f, 0.f};
    int j = 0;
    for (; j + 4 <= deg; j += 4) {
        int2 e0 = g_ell0[base + j],     e1 = g_ell0[base + j + 1];
        int2 e2 = g_ell0[base + j + 2], e3 = g_ell0[base + j + 3];
        uint2 v0 = g_lxh[(unsigned)e0.x * 16u + lane];
        uint2 v1 = g_lxh[(unsigned)e1.x * 16u + lane];
        uint2 v2 = g_lxh[(unsigned)e2.x * 16u + lane];
        uint2 v3 = g_lxh[(unsigned)e3.x * 16u + lane];
        fma4(acc, v0, __int_as_float(e0.y));
        fma4(acc, v1, __int_as_float(e1.y));
        fma4(acc, v2, __int_as_float(e2.y));
        fma4(acc, v3, __int_as_float(e3.y));
    }
    for (; j < deg; j++) {
        int2 e0 = g_ell0[base + j];
        uint2 v0 = g_lxh[(unsigned)e0.x * 16u + lane];
        fma4(acc, v0, __int_as_float(e0.y));
    }
    float t0 = fmaxf(__ldg(temp + 0), 0.f);
    float t1 = fmaxf(__ldg(temp + 1), 0.f);
    float t2 = fmaxf(__ldg(temp + 2), 0.f);
    float c0 = t0;
    float c1 = t1 - t0;
    float c2 = (t0 + t2 - 2.f * t1) * 0.25f;
    float4 xv = *(const float4*)(x + (size_t)r * DD + lane * 4u);
    float4 lv = unpack4(g_lxh[(unsigned)r * 16u + lane]);
    float o0 = c0 * xv.x + c1 * lv.x + c2 * (lv.x - acc[0]);
    float o1 = c0 * xv.y + c1 * lv.y + c2 * (lv.y - acc[1]);
    float o2 = c0 * xv.z + c1 * lv.z + c2 * (lv.z - acc[2]);
    float o3 = c0 * xv.w + c1 * lv.w + c2 * (lv.w - acc[3]);
    *(float4*)(out + (size_t)r * DD + lane * 4u) = make_float4(o0, o1, o2, o3);
    g_outh[(unsigned)r * 16u + lane] = pack4(o0, o1, o2, o3);
}

// dual hop 1: b1h[r] = sum w*outh[col]; b2h[r] = sum w*outh[shuf[col]]
__global__ void spmm_N1_kernel(const int* __restrict__ shuf) {
    int t = blockIdx.x * blockDim.x + threadIdx.x;
    int r = t >> 4;
    if (r >= NN) return;
    unsigned lane = t & 15;
    int deg = g_cnt1[r];
    const size_t base = (size_t)r * WMAX;
    float ap[4] = {0.f, 0.f, 0.f, 0.f};
    float an[4] = {0.f, 0.f, 0.f, 0.f};
    int j = 0;
    for (; j + 4 <= deg; j += 4) {
        int2 e0 = g_ell1[base + j],     e1 = g_ell1[base + j + 1];
        int2 e2 = g_ell1[base + j + 2], e3 = g_ell1[base + j + 3];
        int s0 = __ldg(shuf + e0.x);
        int s1 = __ldg(shuf + e1.x);
        int s2 = __ldg(shuf + e2.x);
        int s3 = __ldg(shuf + e3.x);
        uint2 vp0 = g_outh[(unsigned)e0.x * 16u + lane];
        uint2 vp1 = g_outh[(unsigned)e1.x * 16u + lane];
        uint2 vp2 = g_outh[(unsigned)e2.x * 16u + lane];
        uint2 vp3 = g_outh[(unsigned)e3.x * 16u + lane];
        uint2 vn0 = g_outh[(unsigned)s0 * 16u + lane];
        uint2 vn1 = g_outh[(unsigned)s1 * 16u + lane];
        uint2 vn2 = g_outh[(unsigned)s2 * 16u + lane];
        uint2 vn3 = g_outh[(unsigned)s3 * 16u + lane];
        float w0 = __int_as_float(e0.y), w1 = __int_as_float(e1.y);
        float w2 = __int_as_float(e2.y), w3 = __int_as_float(e3.y);
        fma4(ap, vp0, w0);
        fma4(ap, vp1, w1);
        fma4(ap, vp2, w2);
        fma4(ap, vp3, w3);
        fma4(an, vn0, w0);
        fma4(an, vn1, w1);
        fma4(an, vn2, w2);
        fma4(an, vn3, w3);
    }
    for (; j < deg; j++) {
        int2 e0 = g_ell1[base + j];
        int s0 = __ldg(shuf + e0.x);
        float w0 = __int_as_float(e0.y);
        uint2 vp0 = g_outh[(unsigned)e0.x * 16u + lane];
        uint2 vn0 = g_outh[(unsigned)s0 * 16u + lane];
        fma4(ap, vp0, w0);
        fma4(an, vn0, w0);
    }
    g_b1h[(unsigned)r * 16u + lane] = pack4(ap[0], ap[1], ap[2], ap[3]);
    g_b2h[(unsigned)r * 16u + lane] = pack4(an[0], an[1], an[2], an[3]);
}

// dual hop 2: zp[r] = sum w*b1h[col]; zn[r] = sum w*b2h[col] (fp32 out)
__global__ void spmm_N2_kernel(float* __restrict__ zp, float* __restrict__ zn) {
    int t = blockIdx.x * blockDim.x + threadIdx.x;
    int r = t >> 4;
    if (r >= NN) return;
    unsigned lane = t & 15;
    int deg = g_cnt1[r];
    const size_t base = (size_t)r * WMAX;
    float ap[4] = {0.f, 0.f, 0.f, 0.f};
    float an[4] = {0.f, 0.f, 0.f, 0.f};
    int j = 0;
    for (; j + 4 <= deg; j += 4) {
        int2 e0 = g_ell1[base + j],     e1 = g_ell1[base + j + 1];
        int2 e2 = g_ell1[base + j + 2], e3 = g_ell1[base + j + 3];
        uint2 vp0 = g_b1h[(unsigned)e0.x * 16u + lane];
        uint2 vn0 = g_b2h[(unsigned)e0.x * 16u + lane];
        uint2 vp1 = g_b1h[(unsigned)e1.x * 16u + lane];
        uint2 vn1 = g_b2h[(unsigned)e1.x * 16u + lane];
        uint2 vp2 = g_b1h[(unsigned)e2.x * 16u + lane];
        uint2 vn2 = g_b2h[(unsigned)e2.x * 16u + lane];
        uint2 vp3 = g_b1h[(unsigned)e3.x * 16u + lane];
        uint2 vn3 = g_b2h[(unsigned)e3.x * 16u + lane];
        float w0 = __int_as_float(e0.y), w1 = __int_as_float(e1.y);
        float w2 = __int_as_float(e2.y), w3 = __int_as_float(e3.y);
        fma4(ap, vp0, w0);
        fma4(an, vn0, w0);
        fma4(ap, vp1, w1);
        fma4(an, vn1, w1);
        fma4(ap, vp2, w2);
        fma4(an, vn2, w2);
        fma4(ap, vp3, w3);
        fma4(an, vn3, w3);
    }
    for (; j < deg; j++) {
        int2 e0 = g_ell1[base + j];
        float w0 = __int_as_float(e0.y);
        uint2 vp0 = g_b1h[(unsigned)e0.x * 16u + lane];
        uint2 vn0 = g_b2h[(unsigned)e0.x * 16u + lane];
        fma4(ap, vp0, w0);
        fma4(an, vn0, w0);
    }
    *(float4*)(zp + (size_t)r * DD + lane * 4u) = make_float4(ap[0], ap[1], ap[2], ap[3]);
    *(float4*)(zn + (size_t)r * DD + lane * 4u) = make_float4(an[0], an[1], an[2], an[3]);
}

extern "C" void kernel_launch(void* const* d_in, const int* in_sizes, int n_in,
                              void* d_out, int out_size) {
    const float* x    = (const float*)d_in[0];
    const int*   shuf = (const int*)  d_in[1];
    const int*   ei   = (const int*)  d_in[2];
    const float* ew   = (const float*)d_in[3];
    const int*   ni   = (const int*)  d_in[4];
    const float* nw   = (const float*)d_in[5];
    const float* temp = (const float*)d_in[6];
    float* out = (float*)d_out;   // [out | z_pos | z_neg]

    const int* erow = ei;
    const int* ecol = ei + EE;
    const int* nrow = ni;
    const int* ncol = ni + EE;

    void *p_cnt0, *p_cnt1, *p_degf;
    cudaGetSymbolAddress(&p_cnt0, g_cnt0);
    cudaGetSymbolAddress(&p_cnt1, g_cnt1);
    cudaGetSymbolAddress(&p_degf, g_degf);

    const int TB = 256;
    const int blkN   = (NN + TB - 1) / TB;
    const int blkALL = (2 * EE + NH2 + TB - 1) / TB;
    const int blkR16 = (NN * 16 + TB - 1) / TB;

    // ---- build: zero counters, fused append (both graphs) + fp16 x, dis ----
    cudaMemsetAsync(p_cnt0, 0, NN * sizeof(int), 0);
    cudaMemsetAsync(p_cnt1, 0, NN * sizeof(int), 0);
    cudaMemsetAsync(p_degf, 0, NN * sizeof(float), 0);
    append_all_kernel<<<blkALL, TB>>>(erow, ecol, ew, nrow, ncol, nw, x);
    dis_kernel<<<blkN, TB>>>();

    // ---- spectral polynomial ----
    spmm_L1_kernel<<<blkR16, TB>>>(x);
    spmm_L2_kernel<<<blkR16, TB>>>(x, temp, out);

    // ---- z_pos / z_neg ----
    spmm_N1_kernel<<<blkR16, TB>>>(shuf);
    spmm_N2_kernel<<<blkR16, TB>>>(out + (size_t)ND, out + 2 * (size_t)ND);
}